// round 12
// baseline (speedup 1.0000x reference)
#include <cuda_runtime.h>

#define Bsz 4
#define Tsz 2048
#define Csz 1024
#define Hn  16
#define Dh  64
#define BT  (Bsz * Tsz)     /* 8192 */
#define N3  (3 * Csz)       /* 3072 */

// Scratch (allocation-free rule: __device__ globals)
__device__ float g_q[Bsz * Hn * Tsz * Dh];   // [B,H,T,D]
__device__ float g_k[Bsz * Hn * Tsz * Dh];
__device__ float g_v[Bsz * Hn * Tsz * Dh];
__device__ float g_y[BT * Csz];              // [B,T,C] attention output

// ---------------------------------------------------------------------------
// GEMM 1: qkv = x @ w_attn + b_attn, scatter to g_q/g_k/g_v.
// 128x128x8 tiles, 256 thr, 8 rows x (4+4 split) cols per thread.
// Double-buffered smem; B-fragment reads contiguous float4s.
// R10-proven; ONLY change: minBlocksPerMultiprocessor = 2 (reg cap 128).
// ---------------------------------------------------------------------------
__global__ __launch_bounds__(256, 2) void qkv_gemm(const float* __restrict__ A,
                                                   const float* __restrict__ Bw,
                                                   const float* __restrict__ bias)
{
    __shared__ float As[2][8][128];
    __shared__ float Bs[2][8][128];

    const int tid = threadIdx.x;
    const int bm = blockIdx.y * 128;
    const int bn = blockIdx.x * 128;
    const int tr  = (tid >> 4) * 8;
    const int tc0 = (tid & 15) * 4;      // col group 0; group 1 = tc0 + 64

    float acc[8][8];
#pragma unroll
    for (int i = 0; i < 8; i++)
#pragma unroll
        for (int j = 0; j < 8; j++) acc[i][j] = 0.f;

    const int arow = tid >> 1;
    const int acol = (tid & 1) * 4;
    const int brow = tid >> 5;
    const int bcol = (tid & 31) * 4;

    const float* Ap = A + (size_t)(bm + arow) * Csz + acol;
    const float* Bp = Bw + (size_t)brow * N3 + bn + bcol;

    {   // prologue: chunk 0 -> buffer 0
        float4 a4 = *(const float4*)(Ap);
        float4 b4 = *(const float4*)(Bp);
        As[0][acol + 0][arow] = a4.x;
        As[0][acol + 1][arow] = a4.y;
        As[0][acol + 2][arow] = a4.z;
        As[0][acol + 3][arow] = a4.w;
        *(float4*)&Bs[0][brow][bcol] = b4;
    }
    __syncthreads();

    const int NC = Csz / 8;
    for (int c = 0; c < NC; c++) {
        const int cur = c & 1;
        float4 a4, b4;
        if (c + 1 < NC) {
            a4 = *(const float4*)(Ap + (c + 1) * 8);
            b4 = *(const float4*)(Bp + (size_t)(c + 1) * 8 * N3);
        }

#pragma unroll
        for (int kk = 0; kk < 8; kk++) {
            float4 af0 = *(const float4*)&As[cur][kk][tr];
            float4 af1 = *(const float4*)&As[cur][kk][tr + 4];
            const float af[8] = {af0.x, af0.y, af0.z, af0.w,
                                 af1.x, af1.y, af1.z, af1.w};
            float4 bg0 = *(const float4*)&Bs[cur][kk][tc0];
            float4 bg1 = *(const float4*)&Bs[cur][kk][tc0 + 64];
            const float bf[8] = {bg0.x, bg0.y, bg0.z, bg0.w,
                                 bg1.x, bg1.y, bg1.z, bg1.w};
#pragma unroll
            for (int i = 0; i < 8; i++)
#pragma unroll
                for (int j = 0; j < 8; j++) acc[i][j] += af[i] * bf[j];
        }

        if (c + 1 < NC) {
            const int nxt = cur ^ 1;
            As[nxt][acol + 0][arow] = a4.x;
            As[nxt][acol + 1][arow] = a4.y;
            As[nxt][acol + 2][arow] = a4.z;
            As[nxt][acol + 3][arow] = a4.w;
            *(float4*)&Bs[nxt][brow][bcol] = b4;
        }
        __syncthreads();
    }

#pragma unroll
    for (int i = 0; i < 8; i++) {
        const int row = bm + tr + i;
        const int bb = row >> 11;
        const int t  = row & (Tsz - 1);
#pragma unroll
        for (int j = 0; j < 8; j++) {
            const int n = bn + ((j < 4) ? (tc0 + j) : (tc0 + 60 + j));  // +64+(j-4)
            const float val = acc[i][j] + bias[n];
            const int sec = n >> 10;
            const int c2  = n & 1023;
            const int h = c2 >> 6;
            const int d = c2 & 63;
            float* dst = (sec == 0) ? g_q : (sec == 1) ? g_k : g_v;
            dst[((bb * Hn + h) * Tsz + t) * Dh + d] = val;
        }
    }
}

// ---------------------------------------------------------------------------
// GEMM 2: out = y @ w_proj + b_proj. Same structure, same launch-bounds change.
// ---------------------------------------------------------------------------
__global__ __launch_bounds__(256, 2) void proj_gemm(const float* __restrict__ Bw,
                                                    const float* __restrict__ bias,
                                                    float* __restrict__ out)
{
    __shared__ float As[2][8][128];
    __shared__ float Bs[2][8][128];

    const int tid = threadIdx.x;
    const int bm = blockIdx.y * 128;
    const int bn = blockIdx.x * 128;
    const int tr  = (tid >> 4) * 8;
    const int tc0 = (tid & 15) * 4;

    float acc[8][8];
#pragma unroll
    for (int i = 0; i < 8; i++)
#pragma unroll
        for (int j = 0; j < 8; j++) acc[i][j] = 0.f;

    const int arow = tid >> 1;
    const int acol = (tid & 1) * 4;
    const int brow = tid >> 5;
    const int bcol = (tid & 31) * 4;

    const float* Ap = g_y + (size_t)(bm + arow) * Csz + acol;
    const float* Bp = Bw + (size_t)brow * Csz + bn + bcol;

    {
        float4 a4 = *(const float4*)(Ap);
        float4 b4 = *(const float4*)(Bp);
        As[0][acol + 0][arow] = a4.x;
        As[0][acol + 1][arow] = a4.y;
        As[0][acol + 2][arow] = a4.z;
        As[0][acol + 3][arow] = a4.w;
        *(float4*)&Bs[0][brow][bcol] = b4;
    }
    __syncthreads();

    const int NC = Csz / 8;
    for (int c = 0; c < NC; c++) {
        const int cur = c & 1;
        float4 a4, b4;
        if (c + 1 < NC) {
            a4 = *(const float4*)(Ap + (c + 1) * 8);
            b4 = *(const float4*)(Bp + (size_t)(c + 1) * 8 * Csz);
        }

#pragma unroll
        for (int kk = 0; kk < 8; kk++) {
            float4 af0 = *(const float4*)&As[cur][kk][tr];
            float4 af1 = *(const float4*)&As[cur][kk][tr + 4];
            const float af[8] = {af0.x, af0.y, af0.z, af0.w,
                                 af1.x, af1.y, af1.z, af1.w};
            float4 bg0 = *(const float4*)&Bs[cur][kk][tc0];
            float4 bg1 = *(const float4*)&Bs[cur][kk][tc0 + 64];
            const float bf[8] = {bg0.x, bg0.y, bg0.z, bg0.w,
                                 bg1.x, bg1.y, bg1.z, bg1.w};
#pragma unroll
            for (int i = 0; i < 8; i++)
#pragma unroll
                for (int j = 0; j < 8; j++) acc[i][j] += af[i] * bf[j];
        }

        if (c + 1 < NC) {
            const int nxt = cur ^ 1;
            As[nxt][acol + 0][arow] = a4.x;
            As[nxt][acol + 1][arow] = a4.y;
            As[nxt][acol + 2][arow] = a4.z;
            As[nxt][acol + 3][arow] = a4.w;
            *(float4*)&Bs[nxt][brow][bcol] = b4;
        }
        __syncthreads();
    }

#pragma unroll
    for (int i = 0; i < 8; i++) {
        const int row = bm + tr + i;
#pragma unroll
        for (int j = 0; j < 8; j++) {
            const int n = bn + ((j < 4) ? (tc0 + j) : (tc0 + 60 + j));
            out[(size_t)row * Csz + n] = acc[i][j] + bias[n];
        }
    }
}

// ---------------------------------------------------------------------------
// Flash attention — VERBATIM from the PASSING Round-1/10 kernel (fp32 FFMA).
// ---------------------------------------------------------------------------
extern __shared__ float sm_attn[];

__global__ __launch_bounds__(256) void attn_kernel()
{
    float* Qs = sm_attn;                 // [64][64], pre-scaled by 1/8
    float* Ks = sm_attn + 64 * 64;       // [64][65]; later holds P
    float* Vs = Ks + 64 * 65;            // [64][64]

    const int head = blockIdx.y;
    const int qt = blockIdx.x;
    const float* Qg = g_q + head * (Tsz * Dh);
    const float* Kg = g_k + head * (Tsz * Dh);
    const float* Vg = g_v + head * (Tsz * Dh);

    const int tid = threadIdx.x;
    const int rg = tid >> 4;
    const int cg = tid & 15;
    const int r0 = rg * 4;
    const int c0 = cg * 4;

    float m_i[4], l_i[4], o[4][4];
#pragma unroll
    for (int i = 0; i < 4; i++) {
        m_i[i] = -1e30f;
        l_i[i] = 0.f;
#pragma unroll
        for (int j = 0; j < 4; j++) o[i][j] = 0.f;
    }

    for (int i = tid; i < 64 * 64; i += 256) {
        const int r = i >> 6, d = i & 63;
        Qs[r * 64 + d] = Qg[(qt * 64 + r) * 64 + d] * 0.125f;
    }

    for (int kt = 0; kt <= qt; kt++) {
        __syncthreads();
        for (int i = tid; i < 64 * 64; i += 256) {
            const int r = i >> 6, d = i & 63;
            Ks[r * 65 + d] = Kg[(kt * 64 + r) * 64 + d];
            Vs[r * 64 + d] = Vg[(kt * 64 + r) * 64 + d];
        }
        __syncthreads();

        float s[4][4];
#pragma unroll
        for (int i = 0; i < 4; i++)
#pragma unroll
            for (int j = 0; j < 4; j++) s[i][j] = 0.f;

        for (int dd = 0; dd < 64; dd++) {
            float af[4], bf[4];
#pragma unroll
            for (int i = 0; i < 4; i++) af[i] = Qs[(r0 + i) * 64 + dd];
#pragma unroll
            for (int j = 0; j < 4; j++) bf[j] = Ks[(c0 + j) * 65 + dd];
#pragma unroll
            for (int i = 0; i < 4; i++)
#pragma unroll
                for (int j = 0; j < 4; j++) s[i][j] += af[i] * bf[j];
        }

        if (kt == qt) {
#pragma unroll
            for (int i = 0; i < 4; i++)
#pragma unroll
                for (int j = 0; j < 4; j++)
                    if (c0 + j > r0 + i) s[i][j] = -1e30f;
        }

        __syncthreads();

#pragma unroll
        for (int i = 0; i < 4; i++) {
            float tmax = s[i][0];
#pragma unroll
            for (int j = 1; j < 4; j++) tmax = fmaxf(tmax, s[i][j]);
#pragma unroll
            for (int off = 1; off < 16; off <<= 1)
                tmax = fmaxf(tmax, __shfl_xor_sync(0xffffffffu, tmax, off));

            const float mnew = fmaxf(m_i[i], tmax);
            const float sc = __expf(m_i[i] - mnew);
            m_i[i] = mnew;

            float tsum = 0.f;
#pragma unroll
            for (int j = 0; j < 4; j++) {
                const float p = __expf(s[i][j] - mnew);
                s[i][j] = p;
                tsum += p;
            }
#pragma unroll
            for (int off = 1; off < 16; off <<= 1)
                tsum += __shfl_xor_sync(0xffffffffu, tsum, off);

            l_i[i] = l_i[i] * sc + tsum;
#pragma unroll
            for (int j = 0; j < 4; j++) {
                o[i][j] *= sc;
                Ks[(r0 + i) * 65 + (c0 + j)] = s[i][j];
            }
        }
        __syncthreads();

        for (int kk = 0; kk < 64; kk++) {
            float af[4], bf[4];
#pragma unroll
            for (int i = 0; i < 4; i++) af[i] = Ks[(r0 + i) * 65 + kk];
#pragma unroll
            for (int j = 0; j < 4; j++) bf[j] = Vs[kk * 64 + c0 + j];
#pragma unroll
            for (int i = 0; i < 4; i++)
#pragma unroll
                for (int j = 0; j < 4; j++) o[i][j] += af[i] * bf[j];
        }
    }

    const int b = head >> 4;
    const int h = head & 15;
#pragma unroll
    for (int i = 0; i < 4; i++) {
        const int t = qt * 64 + r0 + i;
        const float inv = 1.f / l_i[i];
#pragma unroll
        for (int j = 0; j < 4; j++)
            g_y[(b * Tsz + t) * Csz + h * 64 + c0 + j] = o[i][j] * inv;
    }
}

// ---------------------------------------------------------------------------

extern "C" void kernel_launch(void* const* d_in, const int* in_sizes, int n_in,
                              void* d_out, int out_size)
{
    (void)in_sizes; (void)n_in; (void)out_size;
    const float* x      = (const float*)d_in[0];
    const float* w_attn = (const float*)d_in[1];
    const float* b_attn = (const float*)d_in[2];
    const float* w_proj = (const float*)d_in[3];
    const float* b_proj = (const float*)d_in[4];
    float* out = (float*)d_out;

    static const size_t ATTN_SMEM = (64 * 64 + 64 * 65 + 64 * 64) * sizeof(float);
    cudaFuncSetAttribute(attn_kernel,
                         cudaFuncAttributeMaxDynamicSharedMemorySize,
                         (int)ATTN_SMEM);

    qkv_gemm<<<dim3(N3 / 128, BT / 128), 256>>>(x, w_attn, b_attn);
    attn_kernel<<<dim3(Tsz / 64, Bsz * Hn), 256, ATTN_SMEM>>>();
    proj_gemm<<<dim3(Csz / 128, BT / 128), 256>>>(w_proj, b_proj, out);
}

// round 13
// speedup vs baseline: 1.1814x; 1.1814x over previous
#include <cuda_runtime.h>

#define Bsz 4
#define Tsz 2048
#define Csz 1024
#define Hn  16
#define Dh  64
#define BT  (Bsz * Tsz)     /* 8192 */
#define N3  (3 * Csz)       /* 3072 */

// Scratch (allocation-free rule: __device__ globals)
__device__ float g_q[Bsz * Hn * Tsz * Dh];   // [B,H,T,D]
__device__ float g_k[Bsz * Hn * Tsz * Dh];
__device__ float g_v[Bsz * Hn * Tsz * Dh];
__device__ float g_y[BT * Csz];              // [B,T,C] attention output

// ---------------------------------------------------------------------------
// GEMM 1: qkv = x @ w_attn + b_attn, scatter to g_q/g_k/g_v.
// 128x128x8 tile, 512 threads, 4 rows x (4+4 split) cols per thread.
// acc = 32 regs -> ~16 warps/SM without any reg cap. Double-buffered smem.
// Threads 0-255 stage A, 256-511 stage B (1 float4 each per chunk).
// ---------------------------------------------------------------------------
__global__ __launch_bounds__(512) void qkv_gemm(const float* __restrict__ A,
                                                const float* __restrict__ Bw,
                                                const float* __restrict__ bias)
{
    __shared__ float As[2][8][128];
    __shared__ float Bs[2][8][128];

    const int tid = threadIdx.x;
    const int bm = blockIdx.y * 128;
    const int bn = blockIdx.x * 128;
    const int tr  = (tid >> 4) * 4;      // 32 row groups x 4 rows
    const int tc0 = (tid & 15) * 4;      // col group 0; group 1 = tc0 + 64

    float acc[4][8];
#pragma unroll
    for (int i = 0; i < 4; i++)
#pragma unroll
        for (int j = 0; j < 8; j++) acc[i][j] = 0.f;

    // staging roles
    const bool stageA = (tid < 256);
    const int arow = tid >> 1;            // 0..127 (A half)
    const int acol = (tid & 1) * 4;       // 0 or 4
    const int bt   = tid - 256;
    const int brow = bt >> 5;             // 0..7   (B half)
    const int bcol = (bt & 31) * 4;       // 0..124

    const float* Ap = A + (size_t)(bm + arow) * Csz + acol;
    const float* Bp = Bw + (size_t)brow * N3 + bn + bcol;

    {   // prologue: chunk 0 -> buffer 0
        if (stageA) {
            float4 a4 = *(const float4*)(Ap);
            As[0][acol + 0][arow] = a4.x;
            As[0][acol + 1][arow] = a4.y;
            As[0][acol + 2][arow] = a4.z;
            As[0][acol + 3][arow] = a4.w;
        } else {
            *(float4*)&Bs[0][brow][bcol] = *(const float4*)(Bp);
        }
    }
    __syncthreads();

    const int NC = Csz / 8;
    for (int c = 0; c < NC; c++) {
        const int cur = c & 1;
        float4 pf;
        if (c + 1 < NC) {
            if (stageA) pf = *(const float4*)(Ap + (c + 1) * 8);
            else        pf = *(const float4*)(Bp + (size_t)(c + 1) * 8 * N3);
        }

#pragma unroll
        for (int kk = 0; kk < 8; kk++) {
            float4 af4 = *(const float4*)&As[cur][kk][tr];
            const float af[4] = {af4.x, af4.y, af4.z, af4.w};
            float4 bg0 = *(const float4*)&Bs[cur][kk][tc0];
            float4 bg1 = *(const float4*)&Bs[cur][kk][tc0 + 64];
            const float bf[8] = {bg0.x, bg0.y, bg0.z, bg0.w,
                                 bg1.x, bg1.y, bg1.z, bg1.w};
#pragma unroll
            for (int i = 0; i < 4; i++)
#pragma unroll
                for (int j = 0; j < 8; j++) acc[i][j] += af[i] * bf[j];
        }

        if (c + 1 < NC) {
            const int nxt = cur ^ 1;
            if (stageA) {
                As[nxt][acol + 0][arow] = pf.x;
                As[nxt][acol + 1][arow] = pf.y;
                As[nxt][acol + 2][arow] = pf.z;
                As[nxt][acol + 3][arow] = pf.w;
            } else {
                *(float4*)&Bs[nxt][brow][bcol] = pf;
            }
        }
        __syncthreads();
    }

#pragma unroll
    for (int i = 0; i < 4; i++) {
        const int row = bm + tr + i;
        const int bb = row >> 11;
        const int t  = row & (Tsz - 1);
#pragma unroll
        for (int j = 0; j < 8; j++) {
            const int n = bn + ((j < 4) ? (tc0 + j) : (tc0 + 60 + j));  // +64+(j-4)
            const float val = acc[i][j] + bias[n];
            const int sec = n >> 10;
            const int c2  = n & 1023;
            const int h = c2 >> 6;
            const int d = c2 & 63;
            float* dst = (sec == 0) ? g_q : (sec == 1) ? g_k : g_v;
            dst[((bb * Hn + h) * Tsz + t) * Dh + d] = val;
        }
    }
}

// ---------------------------------------------------------------------------
// GEMM 2: out = y @ w_proj + b_proj. Same 512-thread structure.
// ---------------------------------------------------------------------------
__global__ __launch_bounds__(512) void proj_gemm(const float* __restrict__ Bw,
                                                 const float* __restrict__ bias,
                                                 float* __restrict__ out)
{
    __shared__ float As[2][8][128];
    __shared__ float Bs[2][8][128];

    const int tid = threadIdx.x;
    const int bm = blockIdx.y * 128;
    const int bn = blockIdx.x * 128;
    const int tr  = (tid >> 4) * 4;
    const int tc0 = (tid & 15) * 4;

    float acc[4][8];
#pragma unroll
    for (int i = 0; i < 4; i++)
#pragma unroll
        for (int j = 0; j < 8; j++) acc[i][j] = 0.f;

    const bool stageA = (tid < 256);
    const int arow = tid >> 1;
    const int acol = (tid & 1) * 4;
    const int bt   = tid - 256;
    const int brow = bt >> 5;
    const int bcol = (bt & 31) * 4;

    const float* Ap = g_y + (size_t)(bm + arow) * Csz + acol;
    const float* Bp = Bw + (size_t)brow * Csz + bn + bcol;

    {
        if (stageA) {
            float4 a4 = *(const float4*)(Ap);
            As[0][acol + 0][arow] = a4.x;
            As[0][acol + 1][arow] = a4.y;
            As[0][acol + 2][arow] = a4.z;
            As[0][acol + 3][arow] = a4.w;
        } else {
            *(float4*)&Bs[0][brow][bcol] = *(const float4*)(Bp);
        }
    }
    __syncthreads();

    const int NC = Csz / 8;
    for (int c = 0; c < NC; c++) {
        const int cur = c & 1;
        float4 pf;
        if (c + 1 < NC) {
            if (stageA) pf = *(const float4*)(Ap + (c + 1) * 8);
            else        pf = *(const float4*)(Bp + (size_t)(c + 1) * 8 * Csz);
        }

#pragma unroll
        for (int kk = 0; kk < 8; kk++) {
            float4 af4 = *(const float4*)&As[cur][kk][tr];
            const float af[4] = {af4.x, af4.y, af4.z, af4.w};
            float4 bg0 = *(const float4*)&Bs[cur][kk][tc0];
            float4 bg1 = *(const float4*)&Bs[cur][kk][tc0 + 64];
            const float bf[8] = {bg0.x, bg0.y, bg0.z, bg0.w,
                                 bg1.x, bg1.y, bg1.z, bg1.w};
#pragma unroll
            for (int i = 0; i < 4; i++)
#pragma unroll
                for (int j = 0; j < 8; j++) acc[i][j] += af[i] * bf[j];
        }

        if (c + 1 < NC) {
            const int nxt = cur ^ 1;
            if (stageA) {
                As[nxt][acol + 0][arow] = pf.x;
                As[nxt][acol + 1][arow] = pf.y;
                As[nxt][acol + 2][arow] = pf.z;
                As[nxt][acol + 3][arow] = pf.w;
            } else {
                *(float4*)&Bs[nxt][brow][bcol] = pf;
            }
        }
        __syncthreads();
    }

#pragma unroll
    for (int i = 0; i < 4; i++) {
        const int row = bm + tr + i;
#pragma unroll
        for (int j = 0; j < 8; j++) {
            const int n = bn + ((j < 4) ? (tc0 + j) : (tc0 + 60 + j));
            out[(size_t)row * Csz + n] = acc[i][j] + bias[j < 4 ? n : n] + 0.f * acc[i][j],
            out[(size_t)row * Csz + n] = acc[i][j] + bias[n];
        }
    }
}

// ---------------------------------------------------------------------------
// Flash attention (fp32, causal). R1 structure + swizzled-K float4 loops.
// Q tile 64, K tile 64, 256 threads, 4x4 micro-tiles.
//   Qs: stride 68 (padded, float4-aligned, conflict-free row-pair reads)
//   Ks: stride 64, XOR-swizzled rows: element (r, c) at Ks[r*64 + (c^(r&60))]
//       -> float4 reads of 4-key columns hit 2 bank groups max.
//   P aliased into Ks with the SAME swizzle (block syncs as in R1).
//   Vs: stride 64 plain; PV reads are float4 over the 4 output cols.
// Accumulation order dd/kk-ascending -> bit-identical to R1.
// Smem: 64*68 + 64*64 + 64*64 floats = 50176 B (dynamic).
// ---------------------------------------------------------------------------
extern __shared__ float sm_attn[];

__global__ __launch_bounds__(256) void attn_kernel()
{
    float* Qs = sm_attn;                 // [64][68], pre-scaled by 1/8
    float* Ks = Qs + 64 * 68;            // [64][64] swizzled; later holds P
    float* Vs = Ks + 64 * 64;            // [64][64]

    const int head = blockIdx.y;
    const int qt = blockIdx.x;
    const float* Qg = g_q + (size_t)head * (Tsz * Dh);
    const float* Kg = g_k + (size_t)head * (Tsz * Dh);
    const float* Vg = g_v + (size_t)head * (Tsz * Dh);

    const int tid = threadIdx.x;
    const int rg = tid >> 4;             // 0..15 row group
    const int cg = tid & 15;             // 0..15 col group
    const int r0 = rg * 4;
    const int c0 = cg * 4;

    float m_i[4], l_i[4], o[4][4];
#pragma unroll
    for (int i = 0; i < 4; i++) {
        m_i[i] = -1e30f;
        l_i[i] = 0.f;
#pragma unroll
        for (int j = 0; j < 4; j++) o[i][j] = 0.f;
    }

    // Load Q tile (scale folded: 1/sqrt(64) = 0.125), stride 68
    for (int i = tid; i < 64 * 16; i += 256) {
        const int r = i >> 4, c = (i & 15) * 4;
        float4 v = *(const float4*)(Qg + (size_t)(qt * 64 + r) * 64 + c);
        float4 w = make_float4(v.x * 0.125f, v.y * 0.125f,
                               v.z * 0.125f, v.w * 0.125f);
        *(float4*)&Qs[r * 68 + c] = w;
    }

    for (int kt = 0; kt <= qt; kt++) {
        __syncthreads();   // prior PV done with Ks/Vs; Q staged (first iter)
        for (int i = tid; i < 64 * 16; i += 256) {
            const int r = i >> 4, c = (i & 15) * 4;
            float4 kv = *(const float4*)(Kg + (size_t)(kt * 64 + r) * 64 + c);
            float4 vv = *(const float4*)(Vg + (size_t)(kt * 64 + r) * 64 + c);
            *(float4*)&Ks[r * 64 + (c ^ (r & 60))] = kv;   // swizzled
            *(float4*)&Vs[r * 64 + c] = vv;
        }
        __syncthreads();

        // S = Q @ K^T (accumulate dd ascending — identical order to R1)
        float s[4][4];
#pragma unroll
        for (int i = 0; i < 4; i++)
#pragma unroll
            for (int j = 0; j < 4; j++) s[i][j] = 0.f;

        for (int dd = 0; dd < 64; dd += 4) {
            float av[4][4], bv[4][4];
#pragma unroll
            for (int i = 0; i < 4; i++) {
                float4 q4 = *(const float4*)&Qs[(r0 + i) * 68 + dd];
                av[i][0] = q4.x; av[i][1] = q4.y; av[i][2] = q4.z; av[i][3] = q4.w;
            }
#pragma unroll
            for (int j = 0; j < 4; j++) {
                const int key = c0 + j;
                float4 k4 = *(const float4*)&Ks[key * 64 + (dd ^ (key & 60))];
                bv[j][0] = k4.x; bv[j][1] = k4.y; bv[j][2] = k4.z; bv[j][3] = k4.w;
            }
#pragma unroll
            for (int i = 0; i < 4; i++)
#pragma unroll
                for (int j = 0; j < 4; j++)
#pragma unroll
                    for (int e = 0; e < 4; e++)
                        s[i][j] += av[i][e] * bv[j][e];
        }

        // Causal mask (diagonal tile only)
        if (kt == qt) {
#pragma unroll
            for (int i = 0; i < 4; i++)
#pragma unroll
                for (int j = 0; j < 4; j++)
                    if (c0 + j > r0 + i) s[i][j] = -1e30f;
        }

        __syncthreads();   // all S reads of Ks done -> safe to overwrite as P

        // Online softmax (identical math to R1)
#pragma unroll
        for (int i = 0; i < 4; i++) {
            float tmax = s[i][0];
#pragma unroll
            for (int j = 1; j < 4; j++) tmax = fmaxf(tmax, s[i][j]);
#pragma unroll
            for (int off = 1; off < 16; off <<= 1)
                tmax = fmaxf(tmax, __shfl_xor_sync(0xffffffffu, tmax, off));

            const float mnew = fmaxf(m_i[i], tmax);
            const float sc = __expf(m_i[i] - mnew);
            m_i[i] = mnew;

            float tsum = 0.f;
#pragma unroll
            for (int j = 0; j < 4; j++) {
                const float p = __expf(s[i][j] - mnew);
                s[i][j] = p;
                tsum += p;
            }
#pragma unroll
            for (int off = 1; off < 16; off <<= 1)
                tsum += __shfl_xor_sync(0xffffffffu, tsum, off);

            l_i[i] = l_i[i] * sc + tsum;
#pragma unroll
            for (int j = 0; j < 4; j++) o[i][j] *= sc;

            // P row store, swizzled like K (c0 mult of 4; xor keeps alignment)
            const int row = r0 + i;
            *(float4*)&Ks[row * 64 + (c0 ^ (row & 60))] =
                make_float4(s[i][0], s[i][1], s[i][2], s[i][3]);
        }
        __syncthreads();

        // O += P @ V (kk ascending — identical order to R1)
        for (int kk = 0; kk < 64; kk += 4) {
            float av[4][4], bv[4][4];
#pragma unroll
            for (int i = 0; i < 4; i++) {
                const int row = r0 + i;
                float4 p4 = *(const float4*)&Ks[row * 64 + (kk ^ (row & 60))];
                av[i][0] = p4.x; av[i][1] = p4.y; av[i][2] = p4.z; av[i][3] = p4.w;
            }
#pragma unroll
            for (int e = 0; e < 4; e++) {
                float4 v4 = *(const float4*)&Vs[(kk + e) * 64 + c0];
                bv[e][0] = v4.x; bv[e][1] = v4.y; bv[e][2] = v4.z; bv[e][3] = v4.w;
            }
#pragma unroll
            for (int i = 0; i < 4; i++)
#pragma unroll
                for (int j = 0; j < 4; j++)
#pragma unroll
                    for (int e = 0; e < 4; e++)
                        o[i][j] += av[i][e] * bv[e][j];
        }
    }

    // Write y in [B,T,C] (head h occupies cols h*64..h*64+63)
    const int b = head >> 4;
    const int h = head & 15;
#pragma unroll
    for (int i = 0; i < 4; i++) {
        const int t = qt * 64 + r0 + i;
        const float inv = 1.f / l_i[i];
#pragma unroll
        for (int j = 0; j < 4; j++)
            g_y[((size_t)b * Tsz + t) * Csz + h * 64 + c0 + j] = o[i][j] * inv;
    }
}

// ---------------------------------------------------------------------------

extern "C" void kernel_launch(void* const* d_in, const int* in_sizes, int n_in,
                              void* d_out, int out_size)
{
    (void)in_sizes; (void)n_in; (void)out_size;
    const float* x      = (const float*)d_in[0];
    const float* w_attn = (const float*)d_in[1];
    const float* b_attn = (const float*)d_in[2];
    const float* w_proj = (const float*)d_in[3];
    const float* b_proj = (const float*)d_in[4];
    float* out = (float*)d_out;

    static const size_t ATTN_SMEM = (size_t)(64 * 68 + 64 * 64 + 64 * 64) * sizeof(float);
    cudaFuncSetAttribute(attn_kernel,
                         cudaFuncAttributeMaxDynamicSharedMemorySize,
                         (int)ATTN_SMEM);

    qkv_gemm<<<dim3(N3 / 128, BT / 128), 512>>>(x, w_attn, b_attn);
    attn_kernel<<<dim3(Tsz / 64, Bsz * Hn), 256, ATTN_SMEM>>>();
    proj_gemm<<<dim3(Csz / 128, BT / 128), 512>>>(w_proj, b_proj, out);
}

// round 14
// speedup vs baseline: 1.5086x; 1.2770x over previous
#include <cuda_runtime.h>

#define Bsz 4
#define Tsz 2048
#define Csz 1024
#define Hn  16
#define Dh  64
#define BT  (Bsz * Tsz)     /* 8192 */
#define N3  (3 * Csz)       /* 3072 */

// Scratch (allocation-free rule: __device__ globals)
__device__ float g_q[Bsz * Hn * Tsz * Dh];   // [B,H,T,D]
__device__ float g_k[Bsz * Hn * Tsz * Dh];
__device__ float g_v[Bsz * Hn * Tsz * Dh];
__device__ float g_y[BT * Csz];              // [B,T,C] attention output

// ---------------------------------------------------------------------------
// GEMM 1 — VERBATIM R10 (best: 1.153 ms): qkv = x @ w_attn + b_attn.
// 128x128x8 tiles, 256 thr, 8 rows x (4+4 split) cols, double-buffered smem.
// ---------------------------------------------------------------------------
__global__ __launch_bounds__(256) void qkv_gemm(const float* __restrict__ A,
                                                const float* __restrict__ Bw,
                                                const float* __restrict__ bias)
{
    __shared__ float As[2][8][128];
    __shared__ float Bs[2][8][128];

    const int tid = threadIdx.x;
    const int bm = blockIdx.y * 128;
    const int bn = blockIdx.x * 128;
    const int tr  = (tid >> 4) * 8;
    const int tc0 = (tid & 15) * 4;      // col group 0; group 1 = tc0 + 64

    float acc[8][8];
#pragma unroll
    for (int i = 0; i < 8; i++)
#pragma unroll
        for (int j = 0; j < 8; j++) acc[i][j] = 0.f;

    const int arow = tid >> 1;
    const int acol = (tid & 1) * 4;
    const int brow = tid >> 5;
    const int bcol = (tid & 31) * 4;

    const float* Ap = A + (size_t)(bm + arow) * Csz + acol;
    const float* Bp = Bw + (size_t)brow * N3 + bn + bcol;

    {   // prologue: chunk 0 -> buffer 0
        float4 a4 = *(const float4*)(Ap);
        float4 b4 = *(const float4*)(Bp);
        As[0][acol + 0][arow] = a4.x;
        As[0][acol + 1][arow] = a4.y;
        As[0][acol + 2][arow] = a4.z;
        As[0][acol + 3][arow] = a4.w;
        *(float4*)&Bs[0][brow][bcol] = b4;
    }
    __syncthreads();

    const int NC = Csz / 8;
    for (int c = 0; c < NC; c++) {
        const int cur = c & 1;
        float4 a4, b4;
        if (c + 1 < NC) {
            a4 = *(const float4*)(Ap + (c + 1) * 8);
            b4 = *(const float4*)(Bp + (size_t)(c + 1) * 8 * N3);
        }

#pragma unroll
        for (int kk = 0; kk < 8; kk++) {
            float4 af0 = *(const float4*)&As[cur][kk][tr];
            float4 af1 = *(const float4*)&As[cur][kk][tr + 4];
            const float af[8] = {af0.x, af0.y, af0.z, af0.w,
                                 af1.x, af1.y, af1.z, af1.w};
            float4 bg0 = *(const float4*)&Bs[cur][kk][tc0];
            float4 bg1 = *(const float4*)&Bs[cur][kk][tc0 + 64];
            const float bf[8] = {bg0.x, bg0.y, bg0.z, bg0.w,
                                 bg1.x, bg1.y, bg1.z, bg1.w};
#pragma unroll
            for (int i = 0; i < 8; i++)
#pragma unroll
                for (int j = 0; j < 8; j++) acc[i][j] += af[i] * bf[j];
        }

        if (c + 1 < NC) {
            const int nxt = cur ^ 1;
            As[nxt][acol + 0][arow] = a4.x;
            As[nxt][acol + 1][arow] = a4.y;
            As[nxt][acol + 2][arow] = a4.z;
            As[nxt][acol + 3][arow] = a4.w;
            *(float4*)&Bs[nxt][brow][bcol] = b4;
        }
        __syncthreads();
    }

#pragma unroll
    for (int i = 0; i < 8; i++) {
        const int row = bm + tr + i;
        const int bb = row >> 11;
        const int t  = row & (Tsz - 1);
#pragma unroll
        for (int j = 0; j < 8; j++) {
            const int n = bn + ((j < 4) ? (tc0 + j) : (tc0 + 60 + j));  // +64+(j-4)
            const float val = acc[i][j] + bias[n];
            const int sec = n >> 10;
            const int c2  = n & 1023;
            const int h = c2 >> 6;
            const int d = c2 & 63;
            float* dst = (sec == 0) ? g_q : (sec == 1) ? g_k : g_v;
            dst[((bb * Hn + h) * Tsz + t) * Dh + d] = val;
        }
    }
}

// ---------------------------------------------------------------------------
// GEMM 2 — VERBATIM R10: out = y @ w_proj + b_proj.
// ---------------------------------------------------------------------------
__global__ __launch_bounds__(256) void proj_gemm(const float* __restrict__ Bw,
                                                 const float* __restrict__ bias,
                                                 float* __restrict__ out)
{
    __shared__ float As[2][8][128];
    __shared__ float Bs[2][8][128];

    const int tid = threadIdx.x;
    const int bm = blockIdx.y * 128;
    const int bn = blockIdx.x * 128;
    const int tr  = (tid >> 4) * 8;
    const int tc0 = (tid & 15) * 4;

    float acc[8][8];
#pragma unroll
    for (int i = 0; i < 8; i++)
#pragma unroll
        for (int j = 0; j < 8; j++) acc[i][j] = 0.f;

    const int arow = tid >> 1;
    const int acol = (tid & 1) * 4;
    const int brow = tid >> 5;
    const int bcol = (tid & 31) * 4;

    const float* Ap = g_y + (size_t)(bm + arow) * Csz + acol;
    const float* Bp = Bw + (size_t)brow * Csz + bn + bcol;

    {
        float4 a4 = *(const float4*)(Ap);
        float4 b4 = *(const float4*)(Bp);
        As[0][acol + 0][arow] = a4.x;
        As[0][acol + 1][arow] = a4.y;
        As[0][acol + 2][arow] = a4.z;
        As[0][acol + 3][arow] = a4.w;
        *(float4*)&Bs[0][brow][bcol] = b4;
    }
    __syncthreads();

    const int NC = Csz / 8;
    for (int c = 0; c < NC; c++) {
        const int cur = c & 1;
        float4 a4, b4;
        if (c + 1 < NC) {
            a4 = *(const float4*)(Ap + (c + 1) * 8);
            b4 = *(const float4*)(Bp + (size_t)(c + 1) * 8 * Csz);
        }

#pragma unroll
        for (int kk = 0; kk < 8; kk++) {
            float4 af0 = *(const float4*)&As[cur][kk][tr];
            float4 af1 = *(const float4*)&As[cur][kk][tr + 4];
            const float af[8] = {af0.x, af0.y, af0.z, af0.w,
                                 af1.x, af1.y, af1.z, af1.w};
            float4 bg0 = *(const float4*)&Bs[cur][kk][tc0];
            float4 bg1 = *(const float4*)&Bs[cur][kk][tc0 + 64];
            const float bf[8] = {bg0.x, bg0.y, bg0.z, bg0.w,
                                 bg1.x, bg1.y, bg1.z, bg1.w};
#pragma unroll
            for (int i = 0; i < 8; i++)
#pragma unroll
                for (int j = 0; j < 8; j++) acc[i][j] += af[i] * bf[j];
        }

        if (c + 1 < NC) {
            const int nxt = cur ^ 1;
            As[nxt][acol + 0][arow] = a4.x;
            As[nxt][acol + 1][arow] = a4.y;
            As[nxt][acol + 2][arow] = a4.z;
            As[nxt][acol + 3][arow] = a4.w;
            *(float4*)&Bs[nxt][brow][bcol] = b4;
        }
        __syncthreads();
    }

#pragma unroll
    for (int i = 0; i < 8; i++) {
        const int row = bm + tr + i;
#pragma unroll
        for (int j = 0; j < 8; j++) {
            const int n = bn + ((j < 4) ? (tc0 + j) : (tc0 + 60 + j));
            out[(size_t)row * Csz + n] = acc[i][j] + bias[n];
        }
    }
}

// ---------------------------------------------------------------------------
// Flash attention — R1 structure + REGISTER PREFETCH of next K/V tile.
// Q tile 64, K tile 64, 256 threads, 4x4 micro-tiles, P aliased into Ks.
// Each thread stages 4 float4 of K and 4 of V per tile (64*16 float4 total).
// Next tile's LDGs are issued right after the staging barrier and consumed
// at the next loop top -> DRAM/L2 latency overlaps with S/softmax/PV compute.
// Smem: Qs[64][64] + Ks[64][65] + Vs[64][64] = 49408 B (dynamic) — unchanged.
// ---------------------------------------------------------------------------
extern __shared__ float sm_attn[];

__global__ __launch_bounds__(256) void attn_kernel()
{
    float* Qs = sm_attn;                 // [64][64], pre-scaled by 1/8
    float* Ks = sm_attn + 64 * 64;       // [64][65]; later holds P
    float* Vs = Ks + 64 * 65;            // [64][64]

    const int head = blockIdx.y;
    const int qt = blockIdx.x;
    const float* Qg = g_q + (size_t)head * (Tsz * Dh);
    const float* Kg = g_k + (size_t)head * (Tsz * Dh);
    const float* Vg = g_v + (size_t)head * (Tsz * Dh);

    const int tid = threadIdx.x;
    const int rg = tid >> 4;
    const int cg = tid & 15;
    const int r0 = rg * 4;
    const int c0 = cg * 4;

    // This thread's 4 staging slots: rows fr[j], col fc (float4 granularity)
    const int fc = (tid & 15) * 4;       // 0..60
    // fr[j] = (tid + j*256) >> 4 = (tid >> 4) + j*16

    float m_i[4], l_i[4], o[4][4];
#pragma unroll
    for (int i = 0; i < 4; i++) {
        m_i[i] = -1e30f;
        l_i[i] = 0.f;
#pragma unroll
        for (int j = 0; j < 4; j++) o[i][j] = 0.f;
    }

    // Load Q tile (scale folded in: 1/sqrt(64) = 0.125)
    for (int i = tid; i < 64 * 64; i += 256) {
        const int r = i >> 6, d = i & 63;
        Qs[r * 64 + d] = Qg[(size_t)(qt * 64 + r) * 64 + d] * 0.125f;
    }

    // Prefetch tile kt=0 into registers
    float4 kvp[4], vvp[4];
#pragma unroll
    for (int j = 0; j < 4; j++) {
        const int r = (tid >> 4) + j * 16;
        kvp[j] = *(const float4*)(Kg + (size_t)r * 64 + fc);
        vvp[j] = *(const float4*)(Vg + (size_t)r * 64 + fc);
    }

    for (int kt = 0; kt <= qt; kt++) {
        __syncthreads();   // prior PV reads of Ks/Vs done; Q staged (first it)
        // Store prefetched tile to smem
#pragma unroll
        for (int j = 0; j < 4; j++) {
            const int r = (tid >> 4) + j * 16;
            float4 kv = kvp[j];
            Ks[r * 65 + fc + 0] = kv.x;
            Ks[r * 65 + fc + 1] = kv.y;
            Ks[r * 65 + fc + 2] = kv.z;
            Ks[r * 65 + fc + 3] = kv.w;
            *(float4*)&Vs[r * 64 + fc] = vvp[j];
        }
        __syncthreads();

        // Issue next tile's loads now; latency hides behind S/softmax/PV
        if (kt + 1 <= qt) {
#pragma unroll
            for (int j = 0; j < 4; j++) {
                const int r = (tid >> 4) + j * 16;
                kvp[j] = *(const float4*)(Kg + (size_t)((kt + 1) * 64 + r) * 64 + fc);
                vvp[j] = *(const float4*)(Vg + (size_t)((kt + 1) * 64 + r) * 64 + fc);
            }
        }

        // S = Q @ K^T
        float s[4][4];
#pragma unroll
        for (int i = 0; i < 4; i++)
#pragma unroll
            for (int j = 0; j < 4; j++) s[i][j] = 0.f;

        for (int dd = 0; dd < 64; dd++) {
            float af[4], bf[4];
#pragma unroll
            for (int i = 0; i < 4; i++) af[i] = Qs[(r0 + i) * 64 + dd];
#pragma unroll
            for (int j = 0; j < 4; j++) bf[j] = Ks[(c0 + j) * 65 + dd];
#pragma unroll
            for (int i = 0; i < 4; i++)
#pragma unroll
                for (int j = 0; j < 4; j++) s[i][j] += af[i] * bf[j];
        }

        // Causal mask (diagonal tile only)
        if (kt == qt) {
#pragma unroll
            for (int i = 0; i < 4; i++)
#pragma unroll
                for (int j = 0; j < 4; j++)
                    if (c0 + j > r0 + i) s[i][j] = -1e30f;
        }

        __syncthreads();   // everyone done reading Ks -> safe to alias as P

        // Online softmax; rows shared by 16 consecutive lanes (half-warp)
#pragma unroll
        for (int i = 0; i < 4; i++) {
            float tmax = s[i][0];
#pragma unroll
            for (int j = 1; j < 4; j++) tmax = fmaxf(tmax, s[i][j]);
#pragma unroll
            for (int off = 1; off < 16; off <<= 1)
                tmax = fmaxf(tmax, __shfl_xor_sync(0xffffffffu, tmax, off));

            const float mnew = fmaxf(m_i[i], tmax);
            const float sc = __expf(m_i[i] - mnew);
            m_i[i] = mnew;

            float tsum = 0.f;
#pragma unroll
            for (int j = 0; j < 4; j++) {
                const float p = __expf(s[i][j] - mnew);
                s[i][j] = p;
                tsum += p;
            }
#pragma unroll
            for (int off = 1; off < 16; off <<= 1)
                tsum += __shfl_xor_sync(0xffffffffu, tsum, off);

            l_i[i] = l_i[i] * sc + tsum;
#pragma unroll
            for (int j = 0; j < 4; j++) {
                o[i][j] *= sc;
                Ks[(r0 + i) * 65 + (c0 + j)] = s[i][j];   // P tile
            }
        }
        __syncthreads();

        // O += P @ V
        for (int kk = 0; kk < 64; kk++) {
            float af[4], bf[4];
#pragma unroll
            for (int i = 0; i < 4; i++) af[i] = Ks[(r0 + i) * 65 + kk];
#pragma unroll
            for (int j = 0; j < 4; j++) bf[j] = Vs[kk * 64 + c0 + j];
#pragma unroll
            for (int i = 0; i < 4; i++)
#pragma unroll
                for (int j = 0; j < 4; j++) o[i][j] += af[i] * bf[j];
        }
    }

    // Write y in [B,T,C] (head h occupies cols h*64..h*64+63)
    const int b = head >> 4;
    const int h = head & 15;
#pragma unroll
    for (int i = 0; i < 4; i++) {
        const int t = qt * 64 + r0 + i;
        const float inv = 1.f / l_i[i];
#pragma unroll
        for (int j = 0; j < 4; j++)
            g_y[((size_t)b * Tsz + t) * Csz + h * 64 + c0 + j] = o[i][j] * inv;
    }
}

// ---------------------------------------------------------------------------

extern "C" void kernel_launch(void* const* d_in, const int* in_sizes, int n_in,
                              void* d_out, int out_size)
{
    (void)in_sizes; (void)n_in; (void)out_size;
    const float* x      = (const float*)d_in[0];
    const float* w_attn = (const float*)d_in[1];
    const float* b_attn = (const float*)d_in[2];
    const float* w_proj = (const float*)d_in[3];
    const float* b_proj = (const float*)d_in[4];
    float* out = (float*)d_out;

    static const size_t ATTN_SMEM = (64 * 64 + 64 * 65 + 64 * 64) * sizeof(float);
    cudaFuncSetAttribute(attn_kernel,
                         cudaFuncAttributeMaxDynamicSharedMemorySize,
                         (int)ATTN_SMEM);

    qkv_gemm<<<dim3(N3 / 128, BT / 128), 256>>>(x, w_attn, b_attn);
    attn_kernel<<<dim3(Tsz / 64, Bsz * Hn), 256, ATTN_SMEM>>>();
    proj_gemm<<<dim3(Csz / 128, BT / 128), 256>>>(w_proj, b_proj, out);
}

// round 15
// speedup vs baseline: 1.5479x; 1.0260x over previous
#include <cuda_runtime.h>

#define Bsz 4
#define Tsz 2048
#define Csz 1024
#define Hn  16
#define Dh  64
#define BT  (Bsz * Tsz)     /* 8192 */
#define N3  (3 * Csz)       /* 3072 */

// Scratch (allocation-free rule: __device__ globals)
__device__ float g_q[Bsz * Hn * Tsz * Dh];   // [B,H,T,D]
__device__ float g_k[Bsz * Hn * Tsz * Dh];
__device__ float g_v[Bsz * Hn * Tsz * Dh];
__device__ float g_y[BT * Csz];              // [B,T,C] attention output

// ---------------------------------------------------------------------------
// GEMM 1 — VERBATIM R10/R14 (best): qkv = x @ w_attn + b_attn.
// ---------------------------------------------------------------------------
__global__ __launch_bounds__(256) void qkv_gemm(const float* __restrict__ A,
                                                const float* __restrict__ Bw,
                                                const float* __restrict__ bias)
{
    __shared__ float As[2][8][128];
    __shared__ float Bs[2][8][128];

    const int tid = threadIdx.x;
    const int bm = blockIdx.y * 128;
    const int bn = blockIdx.x * 128;
    const int tr  = (tid >> 4) * 8;
    const int tc0 = (tid & 15) * 4;      // col group 0; group 1 = tc0 + 64

    float acc[8][8];
#pragma unroll
    for (int i = 0; i < 8; i++)
#pragma unroll
        for (int j = 0; j < 8; j++) acc[i][j] = 0.f;

    const int arow = tid >> 1;
    const int acol = (tid & 1) * 4;
    const int brow = tid >> 5;
    const int bcol = (tid & 31) * 4;

    const float* Ap = A + (size_t)(bm + arow) * Csz + acol;
    const float* Bp = Bw + (size_t)brow * N3 + bn + bcol;

    {   // prologue: chunk 0 -> buffer 0
        float4 a4 = *(const float4*)(Ap);
        float4 b4 = *(const float4*)(Bp);
        As[0][acol + 0][arow] = a4.x;
        As[0][acol + 1][arow] = a4.y;
        As[0][acol + 2][arow] = a4.z;
        As[0][acol + 3][arow] = a4.w;
        *(float4*)&Bs[0][brow][bcol] = b4;
    }
    __syncthreads();

    const int NC = Csz / 8;
    for (int c = 0; c < NC; c++) {
        const int cur = c & 1;
        float4 a4, b4;
        if (c + 1 < NC) {
            a4 = *(const float4*)(Ap + (c + 1) * 8);
            b4 = *(const float4*)(Bp + (size_t)(c + 1) * 8 * N3);
        }

#pragma unroll
        for (int kk = 0; kk < 8; kk++) {
            float4 af0 = *(const float4*)&As[cur][kk][tr];
            float4 af1 = *(const float4*)&As[cur][kk][tr + 4];
            const float af[8] = {af0.x, af0.y, af0.z, af0.w,
                                 af1.x, af1.y, af1.z, af1.w};
            float4 bg0 = *(const float4*)&Bs[cur][kk][tc0];
            float4 bg1 = *(const float4*)&Bs[cur][kk][tc0 + 64];
            const float bf[8] = {bg0.x, bg0.y, bg0.z, bg0.w,
                                 bg1.x, bg1.y, bg1.z, bg1.w};
#pragma unroll
            for (int i = 0; i < 8; i++)
#pragma unroll
                for (int j = 0; j < 8; j++) acc[i][j] += af[i] * bf[j];
        }

        if (c + 1 < NC) {
            const int nxt = cur ^ 1;
            As[nxt][acol + 0][arow] = a4.x;
            As[nxt][acol + 1][arow] = a4.y;
            As[nxt][acol + 2][arow] = a4.z;
            As[nxt][acol + 3][arow] = a4.w;
            *(float4*)&Bs[nxt][brow][bcol] = b4;
        }
        __syncthreads();
    }

#pragma unroll
    for (int i = 0; i < 8; i++) {
        const int row = bm + tr + i;
        const int bb = row >> 11;
        const int t  = row & (Tsz - 1);
#pragma unroll
        for (int j = 0; j < 8; j++) {
            const int n = bn + ((j < 4) ? (tc0 + j) : (tc0 + 60 + j));  // +64+(j-4)
            const float val = acc[i][j] + bias[n];
            const int sec = n >> 10;
            const int c2  = n & 1023;
            const int h = c2 >> 6;
            const int d = c2 & 63;
            float* dst = (sec == 0) ? g_q : (sec == 1) ? g_k : g_v;
            dst[((bb * Hn + h) * Tsz + t) * Dh + d] = val;
        }
    }
}

// ---------------------------------------------------------------------------
// GEMM 2 — VERBATIM R10/R14: out = y @ w_proj + b_proj.
// ---------------------------------------------------------------------------
__global__ __launch_bounds__(256) void proj_gemm(const float* __restrict__ Bw,
                                                 const float* __restrict__ bias,
                                                 float* __restrict__ out)
{
    __shared__ float As[2][8][128];
    __shared__ float Bs[2][8][128];

    const int tid = threadIdx.x;
    const int bm = blockIdx.y * 128;
    const int bn = blockIdx.x * 128;
    const int tr  = (tid >> 4) * 8;
    const int tc0 = (tid & 15) * 4;

    float acc[8][8];
#pragma unroll
    for (int i = 0; i < 8; i++)
#pragma unroll
        for (int j = 0; j < 8; j++) acc[i][j] = 0.f;

    const int arow = tid >> 1;
    const int acol = (tid & 1) * 4;
    const int brow = tid >> 5;
    const int bcol = (tid & 31) * 4;

    const float* Ap = g_y + (size_t)(bm + arow) * Csz + acol;
    const float* Bp = Bw + (size_t)brow * Csz + bn + bcol;

    {
        float4 a4 = *(const float4*)(Ap);
        float4 b4 = *(const float4*)(Bp);
        As[0][acol + 0][arow] = a4.x;
        As[0][acol + 1][arow] = a4.y;
        As[0][acol + 2][arow] = a4.z;
        As[0][acol + 3][arow] = a4.w;
        *(float4*)&Bs[0][brow][bcol] = b4;
    }
    __syncthreads();

    const int NC = Csz / 8;
    for (int c = 0; c < NC; c++) {
        const int cur = c & 1;
        float4 a4, b4;
        if (c + 1 < NC) {
            a4 = *(const float4*)(Ap + (c + 1) * 8);
            b4 = *(const float4*)(Bp + (size_t)(c + 1) * 8 * Csz);
        }

#pragma unroll
        for (int kk = 0; kk < 8; kk++) {
            float4 af0 = *(const float4*)&As[cur][kk][tr];
            float4 af1 = *(const float4*)&As[cur][kk][tr + 4];
            const float af[8] = {af0.x, af0.y, af0.z, af0.w,
                                 af1.x, af1.y, af1.z, af1.w};
            float4 bg0 = *(const float4*)&Bs[cur][kk][tc0];
            float4 bg1 = *(const float4*)&Bs[cur][kk][tc0 + 64];
            const float bf[8] = {bg0.x, bg0.y, bg0.z, bg0.w,
                                 bg1.x, bg1.y, bg1.z, bg1.w};
#pragma unroll
            for (int i = 0; i < 8; i++)
#pragma unroll
                for (int j = 0; j < 8; j++) acc[i][j] += af[i] * bf[j];
        }

        if (c + 1 < NC) {
            const int nxt = cur ^ 1;
            As[nxt][acol + 0][arow] = a4.x;
            As[nxt][acol + 1][arow] = a4.y;
            As[nxt][acol + 2][arow] = a4.z;
            As[nxt][acol + 3][arow] = a4.w;
            *(float4*)&Bs[nxt][brow][bcol] = b4;
        }
        __syncthreads();
    }

#pragma unroll
    for (int i = 0; i < 8; i++) {
        const int row = bm + tr + i;
#pragma unroll
        for (int j = 0; j < 8; j++) {
            const int n = bn + ((j < 4) ? (tc0 + j) : (tc0 + 60 + j));
            out[(size_t)row * Csz + n] = acc[i][j] + bias[n];
        }
    }
}

// ---------------------------------------------------------------------------
// Flash attention — vectorized MMA loops + K/V register prefetch.
// Q tile 64, K tile 64, 256 threads, 4x4 micro-tiles.
//   Qs [64 q][64 d] row-major   -> S-loop Q reads: broadcast LDS.128
//   Kt [64 d][68]   transposed  -> S-loop K reads: conflict-free LDS.128
//      staged via per-thread 4x4 register transpose (coalesced LDG rows)
//   P aliased into Kt region, rows stride 68 -> aligned float4 reads over kk
//   Vs [64 k][64 d] row-major   -> PV V reads: broadcast-safe LDS.128
// Accumulation order dd/kk-ascending -> bit-identical to R1/R14.
// Smem: 4096 + 4352 + 4096 floats = 50176 B (dynamic).
// ---------------------------------------------------------------------------
extern __shared__ float sm_attn[];

__global__ __launch_bounds__(256) void attn_kernel()
{
    float* Qs = sm_attn;                 // [64][64], pre-scaled by 1/8
    float* Kt = Qs + 64 * 64;            // [64][68] transposed K; later holds P
    float* Vs = Kt + 64 * 68;            // [64][64]

    const int head = blockIdx.y;
    const int qt = blockIdx.x;
    const float* Qg = g_q + (size_t)head * (Tsz * Dh);
    const float* Kg = g_k + (size_t)head * (Tsz * Dh);
    const float* Vg = g_v + (size_t)head * (Tsz * Dh);

    const int tid = threadIdx.x;
    const int rg = tid >> 4;             // 0..15 row group
    const int cg = tid & 15;             // 0..15 col group
    const int r0 = rg * 4;
    const int c0 = cg * 4;

    // K staging block for this thread: rows kr4..+3, cols kc4..+3
    const int kr4 = (tid >> 4) * 4;      // 0..60
    const int kc4 = (tid & 15) * 4;      // 0..60
    // V staging slots (row-major): rows (tid>>4)+j*16, col fc
    const int fc = (tid & 15) * 4;

    float m_i[4], l_i[4], o[4][4];
#pragma unroll
    for (int i = 0; i < 4; i++) {
        m_i[i] = -1e30f;
        l_i[i] = 0.f;
#pragma unroll
        for (int j = 0; j < 4; j++) o[i][j] = 0.f;
    }

    // Load Q tile (scale folded in: 1/sqrt(64) = 0.125)
    for (int i = tid; i < 64 * 16; i += 256) {
        const int r = i >> 4, c = (i & 15) * 4;
        float4 v = *(const float4*)(Qg + (size_t)(qt * 64 + r) * 64 + c);
        *(float4*)&Qs[r * 64 + c] = make_float4(v.x * 0.125f, v.y * 0.125f,
                                                v.z * 0.125f, v.w * 0.125f);
    }

    // Prefetch tile kt=0: K 4x4 block + V rows
    float4 kvp[4], vvp[4];
#pragma unroll
    for (int i = 0; i < 4; i++)
        kvp[i] = *(const float4*)(Kg + (size_t)(kr4 + i) * 64 + kc4);
#pragma unroll
    for (int j = 0; j < 4; j++)
        vvp[j] = *(const float4*)(Vg + (size_t)((tid >> 4) + j * 16) * 64 + fc);

    for (int kt = 0; kt <= qt; kt++) {
        __syncthreads();   // prior PV reads of Kt/Vs done; Q staged (first it)
        // Store prefetched K (register 4x4 transpose) + V to smem
        {
            float4 t0 = make_float4(kvp[0].x, kvp[1].x, kvp[2].x, kvp[3].x);
            float4 t1 = make_float4(kvp[0].y, kvp[1].y, kvp[2].y, kvp[3].y);
            float4 t2 = make_float4(kvp[0].z, kvp[1].z, kvp[2].z, kvp[3].z);
            float4 t3 = make_float4(kvp[0].w, kvp[1].w, kvp[2].w, kvp[3].w);
            *(float4*)&Kt[(kc4 + 0) * 68 + kr4] = t0;
            *(float4*)&Kt[(kc4 + 1) * 68 + kr4] = t1;
            *(float4*)&Kt[(kc4 + 2) * 68 + kr4] = t2;
            *(float4*)&Kt[(kc4 + 3) * 68 + kr4] = t3;
#pragma unroll
            for (int j = 0; j < 4; j++)
                *(float4*)&Vs[((tid >> 4) + j * 16) * 64 + fc] = vvp[j];
        }
        __syncthreads();

        // Issue next tile's loads now; latency hides behind S/softmax/PV
        if (kt + 1 <= qt) {
#pragma unroll
            for (int i = 0; i < 4; i++)
                kvp[i] = *(const float4*)(Kg + (size_t)((kt + 1) * 64 + kr4 + i) * 64 + kc4);
#pragma unroll
            for (int j = 0; j < 4; j++)
                vvp[j] = *(const float4*)(Vg + (size_t)((kt + 1) * 64 + (tid >> 4) + j * 16) * 64 + fc);
        }

        // S = Q @ K^T (dd ascending; identical order to R1)
        float s[4][4];
#pragma unroll
        for (int i = 0; i < 4; i++)
#pragma unroll
            for (int j = 0; j < 4; j++) s[i][j] = 0.f;

        for (int dd = 0; dd < 64; dd += 4) {
            float av[4][4], bv[4][4];
#pragma unroll
            for (int i = 0; i < 4; i++) {
                float4 q4 = *(const float4*)&Qs[(r0 + i) * 64 + dd];   // broadcast
                av[i][0] = q4.x; av[i][1] = q4.y; av[i][2] = q4.z; av[i][3] = q4.w;
            }
#pragma unroll
            for (int e = 0; e < 4; e++) {
                float4 k4 = *(const float4*)&Kt[(dd + e) * 68 + c0];   // conflict-free
                bv[e][0] = k4.x; bv[e][1] = k4.y; bv[e][2] = k4.z; bv[e][3] = k4.w;
            }
#pragma unroll
            for (int i = 0; i < 4; i++)
#pragma unroll
                for (int j = 0; j < 4; j++)
#pragma unroll
                    for (int e = 0; e < 4; e++)
                        s[i][j] += av[i][e] * bv[e][j];
        }

        // Causal mask (diagonal tile only)
        if (kt == qt) {
#pragma unroll
            for (int i = 0; i < 4; i++)
#pragma unroll
                for (int j = 0; j < 4; j++)
                    if (c0 + j > r0 + i) s[i][j] = -1e30f;
        }

        __syncthreads();   // all S reads of Kt done -> safe to alias as P

        // Online softmax (identical math to R1)
#pragma unroll
        for (int i = 0; i < 4; i++) {
            float tmax = s[i][0];
#pragma unroll
            for (int j = 1; j < 4; j++) tmax = fmaxf(tmax, s[i][j]);
#pragma unroll
            for (int off = 1; off < 16; off <<= 1)
                tmax = fmaxf(tmax, __shfl_xor_sync(0xffffffffu, tmax, off));

            const float mnew = fmaxf(m_i[i], tmax);
            const float sc = __expf(m_i[i] - mnew);
            m_i[i] = mnew;

            float tsum = 0.f;
#pragma unroll
            for (int j = 0; j < 4; j++) {
                const float p = __expf(s[i][j] - mnew);
                s[i][j] = p;
                tsum += p;
            }
#pragma unroll
            for (int off = 1; off < 16; off <<= 1)
                tsum += __shfl_xor_sync(0xffffffffu, tsum, off);

            l_i[i] = l_i[i] * sc + tsum;
#pragma unroll
            for (int j = 0; j < 4; j++) o[i][j] *= sc;

            // P row store (float4, stride-68 rows in the Kt region)
            *(float4*)&Kt[(r0 + i) * 68 + c0] =
                make_float4(s[i][0], s[i][1], s[i][2], s[i][3]);
        }
        __syncthreads();

        // O += P @ V (kk ascending; identical order to R1)
        for (int kk = 0; kk < 64; kk += 4) {
            float av[4][4], bv[4][4];
#pragma unroll
            for (int i = 0; i < 4; i++) {
                float4 p4 = *(const float4*)&Kt[(r0 + i) * 68 + kk];
                av[i][0] = p4.x; av[i][1] = p4.y; av[i][2] = p4.z; av[i][3] = p4.w;
            }
#pragma unroll
            for (int e = 0; e < 4; e++) {
                float4 v4 = *(const float4*)&Vs[(kk + e) * 64 + c0];
                bv[e][0] = v4.x; bv[e][1] = v4.y; bv[e][2] = v4.z; bv[e][3] = v4.w;
            }
#pragma unroll
            for (int i = 0; i < 4; i++)
#pragma unroll
                for (int j = 0; j < 4; j++)
#pragma unroll
                    for (int e = 0; e < 4; e++)
                        o[i][j] += av[i][e] * bv[e][j];
        }
    }

    // Write y in [B,T,C] (head h occupies cols h*64..h*64+63)
    const int b = head >> 4;
    const int h = head & 15;
#pragma unroll
    for (int i = 0; i < 4; i++) {
        const int t = qt * 64 + r0 + i;
        const float inv = 1.f / l_i[i];
#pragma unroll
        for (int j = 0; j < 4; j++)
            g_y[((size_t)b * Tsz + t) * Csz + h * 64 + c0 + j] = o[i][j] * inv;
    }
}

// ---------------------------------------------------------------------------

extern "C" void kernel_launch(void* const* d_in, const int* in_sizes, int n_in,
                              void* d_out, int out_size)
{
    (void)in_sizes; (void)n_in; (void)out_size;
    const float* x      = (const float*)d_in[0];
    const float* w_attn = (const float*)d_in[1];
    const float* b_attn = (const float*)d_in[2];
    const float* w_proj = (const float*)d_in[3];
    const float* b_proj = (const float*)d_in[4];
    float* out = (float*)d_out;

    static const size_t ATTN_SMEM = (size_t)(64 * 64 + 64 * 68 + 64 * 64) * sizeof(float);
    cudaFuncSetAttribute(attn_kernel,
                         cudaFuncAttributeMaxDynamicSharedMemorySize,
                         (int)ATTN_SMEM);

    qkv_gemm<<<dim3(N3 / 128, BT / 128), 256>>>(x, w_attn, b_attn);
    attn_kernel<<<dim3(Tsz / 64, Bsz * Hn), 256, ATTN_SMEM>>>();
    proj_gemm<<<dim3(Csz / 128, BT / 128), 256>>>(w_proj, b_proj, out);
}